// round 1
// baseline (speedup 1.0000x reference)
#include <cuda_runtime.h>
#include <math.h>

#define NUM_ROWS 12288      // 16 * 768
#define NPT 4096
#define NH  2048
#define NQ  1024
#define MODES 2049
#define LAM 0.01f
#define ORTHO_INV 0.015625f // 1/sqrt(4096)

// Scratch spectrum: [16][768][2049] complex, in-place through the MLP stage.
static __device__ float2 g_spec[(size_t)NUM_ROWS * MODES];

// ---------------------------------------------------------------------------
// Shared-memory radix-2 Stockham FFT, 2048 points, 256 threads.
// Twiddle table wtab[t] = exp(sign * 2*pi*i * t / 2048) baked by caller.
// Caller must __syncthreads() after writing src. Returns buffer holding result.
// ---------------------------------------------------------------------------
__device__ __forceinline__ float2* stockham2048(float2* src, float2* dst,
                                                const float2* __restrict__ wtab,
                                                int tid) {
#pragma unroll
    for (int s = 0; s < 11; s++) {
        const int m = 1 << s;
#pragma unroll
        for (int u = tid; u < NQ; u += 256) {
            float2 c0 = src[u];
            float2 c1 = src[u + NQ];
            float2 w  = wtab[u & ~(m - 1)];
            float2 sum = make_float2(c0.x + c1.x, c0.y + c1.y);
            float2 dif = make_float2(c0.x - c1.x, c0.y - c1.y);
            float2 wd  = make_float2(fmaf(w.x, dif.x, -w.y * dif.y),
                                     fmaf(w.x, dif.y,  w.y * dif.x));
            int o0 = ((u >> s) << (s + 1)) | (u & (m - 1));
            dst[o0]     = sum;
            dst[o0 + m] = wd;
        }
        __syncthreads();
        float2* t = src; src = dst; dst = t;
    }
    return src;
}

// ---------------------------------------------------------------------------
// Kernel 1: rfft(x, norm='ortho') per row via packed half-length complex FFT.
// z[n] = x[2n] + i x[2n+1]; Z = FFT_2048(z); untangle to X[0..2048].
// ---------------------------------------------------------------------------
__global__ void __launch_bounds__(256) kfft_fwd(const float* __restrict__ x) {
    __shared__ float2 bufA[NH];
    __shared__ float2 bufB[NH];
    __shared__ float2 wtab[NQ];
    const int tid = threadIdx.x;
    const int row = blockIdx.x;
    const float2* __restrict__ xin =
        reinterpret_cast<const float2*>(x) + (size_t)row * NH;

#pragma unroll
    for (int i = tid; i < NH; i += 256) bufA[i] = xin[i];
#pragma unroll
    for (int t = tid; t < NQ; t += 256) {
        float s, c;
        sincospif(-(float)t * (2.0f / NH), &s, &c);   // exp(-2*pi*i*t/2048)
        wtab[t] = make_float2(c, s);
    }
    __syncthreads();

    float2* Z = stockham2048(bufA, bufB, wtab, tid);

    float2* __restrict__ out = g_spec + (size_t)row * MODES;
    for (int k = tid; k < MODES; k += 256) {
        int k2 = k & (NH - 1);
        int kr = (NH - k2) & (NH - 1);
        float2 zk = Z[k2];
        float2 zr = Z[kr];
        // Xe = (zk + conj(zr))/2 ; Xo = (zk - conj(zr))/(2i)
        float2 xe = make_float2(0.5f * (zk.x + zr.x), 0.5f * (zk.y - zr.y));
        float2 xo = make_float2(0.5f * (zk.y + zr.y), -0.5f * (zk.x - zr.x));
        float s, c;
        sincospif(-(float)k * (1.0f / NH), &s, &c);   // exp(-2*pi*i*k/4096)
        float2 t = make_float2(fmaf(c, xo.x, -s * xo.y),
                               fmaf(c, xo.y,  s * xo.x));
        out[k] = make_float2((xe.x + t.x) * ORTHO_INV,
                             (xe.y + t.y) * ORTHO_INV);
    }
}

// ---------------------------------------------------------------------------
// Kernel 2: per-mode blockwise complex MLP, in-place on g_spec.
// One CTA per (batch b, block nb). Weights resident in dynamic smem.
// 16 warps; each warp owns one mode at a time; each lane computes 3 outputs.
// ---------------------------------------------------------------------------
__device__ __forceinline__ float softshrink(float v) {
    return v > LAM ? v - LAM : (v < -LAM ? v + LAM : 0.0f);
}

__global__ void __launch_bounds__(512) kmlp(
    const float* __restrict__ w1_re, const float* __restrict__ w1_im,
    const float* __restrict__ w2_re, const float* __restrict__ w2_im,
    const float* __restrict__ b1_re, const float* __restrict__ b1_im,
    const float* __restrict__ b2_re, const float* __restrict__ b2_im)
{
    extern __shared__ float2 smem[];
    float2* sW1  = smem;             // 96*96
    float2* sW2  = sW1 + 9216;       // 96*96
    float2* sB1  = sW2 + 9216;       // 96
    float2* sB2  = sB1 + 96;         // 96
    float2* sBuf = sB2 + 96;         // 16 warps * (96 xf + 96 h)

    const int tid = threadIdx.x;
    const int nb  = blockIdx.x & 7;
    const int b   = blockIdx.x >> 3;
    const int wb  = nb * 9216;

    for (int i = tid; i < 9216; i += 512) {
        sW1[i] = make_float2(w1_re[wb + i], w1_im[wb + i]);
        sW2[i] = make_float2(w2_re[wb + i], w2_im[wb + i]);
    }
    if (tid < 96) {
        sB1[tid] = make_float2(b1_re[nb * 96 + tid], b1_im[nb * 96 + tid]);
        sB2[tid] = make_float2(b2_re[nb * 96 + tid], b2_im[nb * 96 + tid]);
    }
    __syncthreads();

    const int warp = tid >> 5;
    const int lane = tid & 31;
    float2* sxf = sBuf + warp * 192;
    float2* sh  = sxf + 96;
    const size_t rowbase = ((size_t)b * 768 + (size_t)nb * 96) * MODES;

    for (int m = warp; m < MODES; m += 16) {
        sxf[lane]      = g_spec[rowbase + (size_t)lane        * MODES + m];
        sxf[lane + 32] = g_spec[rowbase + (size_t)(lane + 32) * MODES + m];
        sxf[lane + 64] = g_spec[rowbase + (size_t)(lane + 64) * MODES + m];
        __syncwarp();

        // h[o] = sum_i xf[i] * W1[i][o] + b1[o]
        float2 a0 = sB1[lane], a1 = sB1[lane + 32], a2 = sB1[lane + 64];
#pragma unroll 8
        for (int i = 0; i < 96; i++) {
            float2 xv = sxf[i];
            float nxy = -xv.y;
            const float2* wr = sW1 + i * 96 + lane;
            float2 w0 = wr[0], w1v = wr[32], w2v = wr[64];
            a0.x = fmaf(xv.x, w0.x,  fmaf(nxy,  w0.y,  a0.x));
            a0.y = fmaf(xv.x, w0.y,  fmaf(xv.y, w0.x,  a0.y));
            a1.x = fmaf(xv.x, w1v.x, fmaf(nxy,  w1v.y, a1.x));
            a1.y = fmaf(xv.x, w1v.y, fmaf(xv.y, w1v.x, a1.y));
            a2.x = fmaf(xv.x, w2v.x, fmaf(nxy,  w2v.y, a2.x));
            a2.y = fmaf(xv.x, w2v.y, fmaf(xv.y, w2v.x, a2.y));
        }
        // CReLU (relu on re/im independently)
        a0.x = fmaxf(a0.x, 0.f); a0.y = fmaxf(a0.y, 0.f);
        a1.x = fmaxf(a1.x, 0.f); a1.y = fmaxf(a1.y, 0.f);
        a2.x = fmaxf(a2.x, 0.f); a2.y = fmaxf(a2.y, 0.f);
        sh[lane] = a0; sh[lane + 32] = a1; sh[lane + 64] = a2;
        __syncwarp();

        // o[o] = sum_i h[i] * W2[i][o] + b2[o]
        float2 o0 = sB2[lane], o1 = sB2[lane + 32], o2 = sB2[lane + 64];
#pragma unroll 8
        for (int i = 0; i < 96; i++) {
            float2 hv = sh[i];
            float nhy = -hv.y;
            const float2* wr = sW2 + i * 96 + lane;
            float2 w0 = wr[0], w1v = wr[32], w2v = wr[64];
            o0.x = fmaf(hv.x, w0.x,  fmaf(nhy,  w0.y,  o0.x));
            o0.y = fmaf(hv.x, w0.y,  fmaf(hv.y, w0.x,  o0.y));
            o1.x = fmaf(hv.x, w1v.x, fmaf(nhy,  w1v.y, o1.x));
            o1.y = fmaf(hv.x, w1v.y, fmaf(hv.y, w1v.x, o1.y));
            o2.x = fmaf(hv.x, w2v.x, fmaf(nhy,  w2v.y, o2.x));
            o2.y = fmaf(hv.x, w2v.y, fmaf(hv.y, w2v.x, o2.y));
        }
        g_spec[rowbase + (size_t)lane        * MODES + m] =
            make_float2(softshrink(o0.x), softshrink(o0.y));
        g_spec[rowbase + (size_t)(lane + 32) * MODES + m] =
            make_float2(softshrink(o1.x), softshrink(o1.y));
        g_spec[rowbase + (size_t)(lane + 64) * MODES + m] =
            make_float2(softshrink(o2.x), softshrink(o2.y));
    }
}

// ---------------------------------------------------------------------------
// Kernel 3: irfft(X, n=4096, norm='ortho') per row + residual add.
// C[j] = (X[j]+X[j+2048]) + i * (X[j]-X[j+2048]) * exp(+2*pi*i*j/4096),
// with X[j+2048] = conj(X[2048-j]); inverse FFT_2048 gives packed
// z[n] = x[2n] + i x[2n+1]. DC/Nyquist imag parts contribute only an
// imaginary component to the output, so zeroing them == irfft semantics.
// ---------------------------------------------------------------------------
__global__ void __launch_bounds__(256) kfft_inv(const float* __restrict__ x,
                                                float* __restrict__ y) {
    __shared__ float2 bufA[NH];
    __shared__ float2 bufB[NH];
    __shared__ float2 wtab[NQ];
    const int tid = threadIdx.x;
    const int row = blockIdx.x;
    const float2* __restrict__ spec = g_spec + (size_t)row * MODES;

#pragma unroll
    for (int t = tid; t < NQ; t += 256) {
        float s, c;
        sincospif((float)t * (2.0f / NH), &s, &c);    // exp(+2*pi*i*t/2048)
        wtab[t] = make_float2(c, s);
    }
    for (int j = tid; j < NH; j += 256) {
        float2 xj = spec[j];
        float2 xr = spec[NH - j];   // j=0 -> spec[2048] (Nyquist)
        if (j == 0) { xj.y = 0.0f; xr.y = 0.0f; }
        float2 A = make_float2(xj.x + xr.x, xj.y - xr.y);  // X[j] + conj(X[2048-j])
        float2 D = make_float2(xj.x - xr.x, xj.y + xr.y);  // X[j] - conj(X[2048-j])
        float s, c;
        sincospif((float)j * (1.0f / NH), &s, &c);    // exp(+2*pi*i*j/4096)
        float2 Bv = make_float2(fmaf(c, D.x, -s * D.y),
                                fmaf(c, D.y,  s * D.x));
        bufA[j] = make_float2(A.x - Bv.y, A.y + Bv.x);     // A + i*B
    }
    __syncthreads();

    float2* Zr = stockham2048(bufA, bufB, wtab, tid);

    const float2* __restrict__ xin =
        reinterpret_cast<const float2*>(x) + (size_t)row * NH;
    float2* __restrict__ yout =
        reinterpret_cast<float2*>(y) + (size_t)row * NH;
    for (int n = tid; n < NH; n += 256) {
        float2 z  = Zr[n];
        float2 bv = xin[n];
        yout[n] = make_float2(fmaf(z.x, ORTHO_INV, bv.x),
                              fmaf(z.y, ORTHO_INV, bv.y));
    }
}

// ---------------------------------------------------------------------------
extern "C" void kernel_launch(void* const* d_in, const int* in_sizes, int n_in,
                              void* d_out, int out_size) {
    (void)in_sizes; (void)n_in; (void)out_size;
    const float* x     = (const float*)d_in[0];
    const float* w1_re = (const float*)d_in[1];
    const float* w1_im = (const float*)d_in[2];
    const float* w2_re = (const float*)d_in[3];
    const float* w2_im = (const float*)d_in[4];
    const float* b1_re = (const float*)d_in[5];
    const float* b1_im = (const float*)d_in[6];
    const float* b2_re = (const float*)d_in[7];
    const float* b2_im = (const float*)d_in[8];
    float* y = (float*)d_out;

    kfft_fwd<<<NUM_ROWS, 256>>>(x);

    const size_t smem2 = (size_t)(9216 * 2 + 192 + 16 * 192) * sizeof(float2);
    cudaFuncSetAttribute(kmlp, cudaFuncAttributeMaxDynamicSharedMemorySize,
                         (int)smem2);
    kmlp<<<128, 512, smem2>>>(w1_re, w1_im, w2_re, w2_im,
                              b1_re, b1_im, b2_re, b2_im);

    kfft_inv<<<NUM_ROWS, 256>>>(x, y);
}

// round 6
// speedup vs baseline: 2.5182x; 2.5182x over previous
#include <cuda_runtime.h>
#include <cuda_bf16.h>
#include <math.h>
#include <stdint.h>

#define NUM_ROWS 12288      // 16 * 768
#define NPT 4096
#define NH  2048
#define NQ  1024
#define MODES 2049
#define LAM 0.01f
#define ORTHO_INV 0.015625f // 1/sqrt(4096)

// bf16x2 spectrum (MLP input), channel-major [row_ch][mode]
static __device__ __nv_bfloat162 g_specA[(size_t)NUM_ROWS * MODES];
// fp32 MLP output spectrum, channel-major [row_ch][mode]
static __device__ float2 g_specO[(size_t)NUM_ROWS * MODES];

// ===========================================================================
// Shared-memory radix-2 Stockham FFT, 2048 points, 256 threads.
// ===========================================================================
__device__ __forceinline__ float2* stockham2048(float2* src, float2* dst,
                                                const float2* __restrict__ wtab,
                                                int tid) {
#pragma unroll
    for (int s = 0; s < 11; s++) {
        const int m = 1 << s;
#pragma unroll
        for (int u = tid; u < NQ; u += 256) {
            float2 c0 = src[u];
            float2 c1 = src[u + NQ];
            float2 w  = wtab[u & ~(m - 1)];
            float2 sum = make_float2(c0.x + c1.x, c0.y + c1.y);
            float2 dif = make_float2(c0.x - c1.x, c0.y - c1.y);
            float2 wd  = make_float2(fmaf(w.x, dif.x, -w.y * dif.y),
                                     fmaf(w.x, dif.y,  w.y * dif.x));
            int o0 = ((u >> s) << (s + 1)) | (u & (m - 1));
            dst[o0]     = sum;
            dst[o0 + m] = wd;
        }
        __syncthreads();
        float2* t = src; src = dst; dst = t;
    }
    return src;
}

// ---------------------------------------------------------------------------
// Kernel 1: rfft(x, ortho) -> bf16x2 spectrum (channel-major)
// ---------------------------------------------------------------------------
__global__ void __launch_bounds__(256) kfft_fwd(const float* __restrict__ x) {
    __shared__ float2 bufA[NH];
    __shared__ float2 bufB[NH];
    __shared__ float2 wtab[NQ];
    const int tid = threadIdx.x;
    const int row = blockIdx.x;
    const float2* __restrict__ xin =
        reinterpret_cast<const float2*>(x) + (size_t)row * NH;

#pragma unroll
    for (int i = tid; i < NH; i += 256) bufA[i] = xin[i];
#pragma unroll
    for (int t = tid; t < NQ; t += 256) {
        float s, c;
        sincospif(-(float)t * (2.0f / NH), &s, &c);
        wtab[t] = make_float2(c, s);
    }
    __syncthreads();

    float2* Z = stockham2048(bufA, bufB, wtab, tid);

    __nv_bfloat162* __restrict__ out = g_specA + (size_t)row * MODES;
    for (int k = tid; k < MODES; k += 256) {
        int k2 = k & (NH - 1);
        int kr = (NH - k2) & (NH - 1);
        float2 zk = Z[k2];
        float2 zr = Z[kr];
        float2 xe = make_float2(0.5f * (zk.x + zr.x), 0.5f * (zk.y - zr.y));
        float2 xo = make_float2(0.5f * (zk.y + zr.y), -0.5f * (zk.x - zr.x));
        float s, c;
        sincospif(-(float)k * (1.0f / NH), &s, &c);
        float2 t = make_float2(fmaf(c, xo.x, -s * xo.y),
                               fmaf(c, xo.y,  s * xo.x));
        out[k] = __floats2bfloat162_rn((xe.x + t.x) * ORTHO_INV,
                                       (xe.y + t.y) * ORTHO_INV);
    }
}

// ---------------------------------------------------------------------------
// Kernel 2: blockwise complex 2-layer MLP via mma.sync (bf16 HMMA).
//
// Complex matmul lifted to real: input row per mode is interleaved
// [re0,im0,...,re95,im95] (192), weight B[o][k] with the [[re,im],[-im,re]]
// block structure, so D = A x B^T(col-major) gives interleaved outputs.
//
// CTA = (batch b, block nb); 8 warps x 16 modes; 24 n-tiles of m16n8k16.
// Layer-1 accumulators convert IN REGISTERS to layer-2 A fragments
// (two adjacent n8 acc tiles == one k16 A fragment).
//
// smem word layout (uint32 units, rows padded to 100 words = 200 bf16):
//   W1:      [0      .. 19200)   192 rows x 100
//   W2:      [19200  .. 38400)
//   A tile:  [38400  .. 51200)   128 rows x 100
//   b1:      [51200  .. 51392)   192 floats
//   b2:      [51392  .. 51584)
// ---------------------------------------------------------------------------
__device__ __forceinline__ float softshrink(float v) {
    return v > LAM ? v - LAM : (v < -LAM ? v + LAM : 0.0f);
}

#define SMEM_MLP_WORDS 51584
#define SMEM_MLP_BYTES (SMEM_MLP_WORDS * 4)
#define W2_BASE 19200
#define A_BASE  38400

#define MMA16816(C, A, B0, B1)                                              \
    asm volatile("mma.sync.aligned.m16n8k16.row.col.f32.bf16.bf16.f32 "     \
        "{%0,%1,%2,%3}, {%4,%5,%6,%7}, {%8,%9}, {%0,%1,%2,%3};"             \
        : "+f"((C)[0]), "+f"((C)[1]), "+f"((C)[2]), "+f"((C)[3])            \
        : "r"((A)[0]), "r"((A)[1]), "r"((A)[2]), "r"((A)[3]),               \
          "r"(B0), "r"(B1))

__global__ void __launch_bounds__(256, 1) kmlp_mma(
    const float* __restrict__ w1_re, const float* __restrict__ w1_im,
    const float* __restrict__ w2_re, const float* __restrict__ w2_im,
    const float* __restrict__ b1_re, const float* __restrict__ b1_im,
    const float* __restrict__ b2_re, const float* __restrict__ b2_im)
{
    extern __shared__ uint32_t smw[];
    __nv_bfloat16* w16 = reinterpret_cast<__nv_bfloat16*>(smw);
    float* sB1 = reinterpret_cast<float*>(smw + 51200);
    float* sB2 = reinterpret_cast<float*>(smw + 51392);

    const int tid  = threadIdx.x;
    const int warp = tid >> 5;
    const int lane = tid & 31;
    const int qr   = lane >> 2;   // 0..7
    const int qc   = lane & 3;    // 0..3
    const int nb   = blockIdx.x & 7;
    const int b    = blockIdx.x >> 3;

    // Build both interleaved weight matrices (B operand, [o][k], stride 200)
    const int wb = nb * 9216;
    for (int idx = tid; idx < 192 * 192; idx += 256) {
        int o = idx / 192, k = idx - o * 192;
        int i = k >> 1, j = o >> 1;
        float re1 = w1_re[wb + i * 96 + j], im1 = w1_im[wb + i * 96 + j];
        float re2 = w2_re[wb + i * 96 + j], im2 = w2_im[wb + i * 96 + j];
        float v1 = (k & 1) ? ((o & 1) ? re1 : -im1) : ((o & 1) ? im1 : re1);
        float v2 = (k & 1) ? ((o & 1) ? re2 : -im2) : ((o & 1) ? im2 : re2);
        w16[o * 200 + k]               = __float2bfloat16(v1);
        w16[W2_BASE * 2 + o * 200 + k] = __float2bfloat16(v2);
    }
    if (tid < 96) {
        sB1[2 * tid] = b1_re[nb * 96 + tid]; sB1[2 * tid + 1] = b1_im[nb * 96 + tid];
        sB2[2 * tid] = b2_re[nb * 96 + tid]; sB2[2 * tid + 1] = b2_im[nb * 96 + tid];
    }

    const size_t chbase = (size_t)b * 768 + (size_t)nb * 96;
    const uint32_t* __restrict__ specA = reinterpret_cast<const uint32_t*>(g_specA);

    for (int tile = 0; tile < 17; tile++) {
        const int m0 = tile * 128;
        __syncthreads();   // prior-tile readers done (and weight build on iter 0)
        // ---- stage A tile: 128 modes x 96 channels (bf16x2 per channel)
        for (int idx = tid; idx < 96 * 128; idx += 256) {
            int ch = idx >> 7, r = idx & 127;
            int m = m0 + r;
            uint32_t v = (m < MODES) ? specA[(chbase + ch) * MODES + m] : 0u;
            smw[A_BASE + r * 100 + ch] = v;
        }
        __syncthreads();

        const int rw = warp * 16 + qr;   // A row for a0 within tile
        float acc[24][4];
#pragma unroll
        for (int nt = 0; nt < 24; nt++)
#pragma unroll
            for (int j = 0; j < 4; j++) acc[nt][j] = 0.0f;

        // ---- layer 1: acc = A x W1
        for (int kk = 0; kk < 12; kk++) {
            const int aw = A_BASE + rw * 100 + kk * 8 + qc;
            uint32_t a[4];
            a[0] = smw[aw];       a[1] = smw[aw + 800];
            a[2] = smw[aw + 4];   a[3] = smw[aw + 804];
            const int bw = qr * 100 + kk * 8 + qc;
#pragma unroll
            for (int nt = 0; nt < 24; nt++) {
                uint32_t b0 = smw[bw + nt * 800];
                uint32_t b1 = smw[bw + nt * 800 + 4];
                MMA16816(acc[nt], a, b0, b1);
            }
        }

        // ---- interlayer: bias + CReLU, pack accs into layer-2 A fragments
        uint32_t af[12][4];
#pragma unroll
        for (int nt = 0; nt < 24; nt++) {
            int col = nt * 8 + 2 * qc;
            float2 bv = *reinterpret_cast<float2*>(&sB1[col]);
            float f0 = fmaxf(acc[nt][0] + bv.x, 0.0f);
            float f1 = fmaxf(acc[nt][1] + bv.y, 0.0f);
            float f2 = fmaxf(acc[nt][2] + bv.x, 0.0f);
            float f3 = fmaxf(acc[nt][3] + bv.y, 0.0f);
            __nv_bfloat162 p01 = __floats2bfloat162_rn(f0, f1);
            __nv_bfloat162 p23 = __floats2bfloat162_rn(f2, f3);
            af[nt >> 1][(nt & 1) ? 2 : 0] = *reinterpret_cast<uint32_t*>(&p01);
            af[nt >> 1][(nt & 1) ? 3 : 1] = *reinterpret_cast<uint32_t*>(&p23);
        }

        // ---- layer 2: acc = CReLU(h) x W2
#pragma unroll
        for (int nt = 0; nt < 24; nt++)
#pragma unroll
            for (int j = 0; j < 4; j++) acc[nt][j] = 0.0f;
#pragma unroll
        for (int kk = 0; kk < 12; kk++) {
            const int bw = W2_BASE + qr * 100 + kk * 8 + qc;
#pragma unroll
            for (int nt = 0; nt < 24; nt++) {
                uint32_t b0 = smw[bw + nt * 800];
                uint32_t b1 = smw[bw + nt * 800 + 4];
                MMA16816(acc[nt], af[kk], b0, b1);
            }
        }

        // ---- epilogue: bias + softshrink, scatter float2 to g_specO
        const int mlo = m0 + warp * 16 + qr;
        const int mhi = mlo + 8;
        const bool vlo = mlo < MODES, vhi = mhi < MODES;
#pragma unroll
        for (int nt = 0; nt < 24; nt++) {
            int col = nt * 8 + 2 * qc;
            int ch  = col >> 1;
            float2 bv = *reinterpret_cast<float2*>(&sB2[col]);
            size_t base = (chbase + ch) * MODES;
            if (vlo)
                g_specO[base + mlo] = make_float2(softshrink(acc[nt][0] + bv.x),
                                                  softshrink(acc[nt][1] + bv.y));
            if (vhi)
                g_specO[base + mhi] = make_float2(softshrink(acc[nt][2] + bv.x),
                                                  softshrink(acc[nt][3] + bv.y));
        }
    }
}

// ---------------------------------------------------------------------------
// Kernel 3: irfft(ortho) per row + residual add, reads g_specO.
// ---------------------------------------------------------------------------
__global__ void __launch_bounds__(256) kfft_inv(const float* __restrict__ x,
                                                float* __restrict__ y) {
    __shared__ float2 bufA[NH];
    __shared__ float2 bufB[NH];
    __shared__ float2 wtab[NQ];
    const int tid = threadIdx.x;
    const int row = blockIdx.x;
    const float2* __restrict__ spec = g_specO + (size_t)row * MODES;

#pragma unroll
    for (int t = tid; t < NQ; t += 256) {
        float s, c;
        sincospif((float)t * (2.0f / NH), &s, &c);
        wtab[t] = make_float2(c, s);
    }
    for (int j = tid; j < NH; j += 256) {
        float2 xj = spec[j];
        float2 xr = spec[NH - j];
        if (j == 0) { xj.y = 0.0f; xr.y = 0.0f; }
        float2 A = make_float2(xj.x + xr.x, xj.y - xr.y);
        float2 D = make_float2(xj.x - xr.x, xj.y + xr.y);
        float s, c;
        sincospif((float)j * (1.0f / NH), &s, &c);
        float2 Bv = make_float2(fmaf(c, D.x, -s * D.y),
                                fmaf(c, D.y,  s * D.x));
        bufA[j] = make_float2(A.x - Bv.y, A.y + Bv.x);
    }
    __syncthreads();

    float2* Zr = stockham2048(bufA, bufB, wtab, tid);

    const float2* __restrict__ xin =
        reinterpret_cast<const float2*>(x) + (size_t)row * NH;
    float2* __restrict__ yout =
        reinterpret_cast<float2*>(y) + (size_t)row * NH;
    for (int n = tid; n < NH; n += 256) {
        float2 z  = Zr[n];
        float2 bv = xin[n];
        yout[n] = make_float2(fmaf(z.x, ORTHO_INV, bv.x),
                              fmaf(z.y, ORTHO_INV, bv.y));
    }
}

// ---------------------------------------------------------------------------
extern "C" void kernel_launch(void* const* d_in, const int* in_sizes, int n_in,
                              void* d_out, int out_size) {
    (void)in_sizes; (void)n_in; (void)out_size;
    const float* x     = (const float*)d_in[0];
    const float* w1_re = (const float*)d_in[1];
    const float* w1_im = (const float*)d_in[2];
    const float* w2_re = (const float*)d_in[3];
    const float* w2_im = (const float*)d_in[4];
    const float* b1_re = (const float*)d_in[5];
    const float* b1_im = (const float*)d_in[6];
    const float* b2_re = (const float*)d_in[7];
    const float* b2_im = (const float*)d_in[8];
    float* y = (float*)d_out;

    kfft_fwd<<<NUM_ROWS, 256>>>(x);

    cudaFuncSetAttribute(kmlp_mma, cudaFuncAttributeMaxDynamicSharedMemorySize,
                         SMEM_MLP_BYTES);
    kmlp_mma<<<128, 256, SMEM_MLP_BYTES>>>(w1_re, w1_im, w2_re, w2_im,
                                           b1_re, b1_im, b2_re, b2_im);

    kfft_inv<<<NUM_ROWS, 256>>>(x, y);
}

// round 10
// speedup vs baseline: 2.8322x; 1.1247x over previous
#include <cuda_runtime.h>
#include <cuda_bf16.h>
#include <math.h>
#include <stdint.h>

#define NUM_ROWS 12288      // 16 * 768
#define NPT 4096
#define NH  2048
#define NQ  1024
#define MODES 2049
#define LAM 0.01f
#define ORTHO_INV 0.015625f // 1/sqrt(4096)

// bf16x2 spectrum (MLP input), channel-major [row_ch][mode]
static __device__ __nv_bfloat162 g_specA[(size_t)NUM_ROWS * MODES];
// fp32 MLP output spectrum, channel-major [row_ch][mode]
static __device__ float2 g_specO[(size_t)NUM_ROWS * MODES];

__device__ __forceinline__ float2 cmul(float2 a, float2 b) {
    return make_float2(fmaf(a.x, b.x, -a.y * b.y), fmaf(a.x, b.y, a.y * b.x));
}
__device__ __forceinline__ float2 cadd(float2 a, float2 b) {
    return make_float2(a.x + b.x, a.y + b.y);
}
__device__ __forceinline__ float2 csub(float2 a, float2 b) {
    return make_float2(a.x - b.x, a.y - b.y);
}

// ===========================================================================
// Shared-memory Stockham FFT, 2048 points, 256 threads.
// 5 fused double-stages (radix-4 style, one smem round-trip per PAIR of
// radix-2 stages) + 1 final radix-2 stage. INV=false: exp(-2pi i/2048) table,
// INV=true: exp(+2pi i/2048) table (caller bakes wtab accordingly).
// Second-butterfly twiddle is (-+i)*w, stage s+1 twiddle is w^2.
// ===========================================================================
template <bool INV>
__device__ __forceinline__ float2* stockham2048_r4(float2* src, float2* dst,
                                                   const float2* __restrict__ wtab,
                                                   int tid) {
#pragma unroll
    for (int s = 0; s < 10; s += 2) {
        const int m = 1 << s;
#pragma unroll
        for (int u = tid; u < 512; u += 256) {
            float2 z0 = src[u];
            float2 z1 = src[u + 512];
            float2 z2 = src[u + 1024];
            float2 z3 = src[u + 1536];
            float2 w  = wtab[(u >> s) << s];

            // stage s butterflies
            float2 e0 = cadd(z0, z2);
            float2 e1 = cmul(w, csub(z0, z2));
            float2 f0 = cadd(z1, z3);
            float2 t1 = cmul(w, csub(z1, z3));
            // f1 = (INV ? +i : -i) * t1
            float2 f1 = INV ? make_float2(-t1.y, t1.x)
                            : make_float2( t1.y, -t1.x);

            // stage s+1 twiddle = w^2
            float2 wc = make_float2(fmaf(w.x, w.x, -w.y * w.y), 2.0f * w.x * w.y);

            int p0 = ((u >> s) << (s + 2)) | (u & (m - 1));
            dst[p0]         = cadd(e0, f0);
            dst[p0 + m]     = cadd(e1, f1);
            dst[p0 + 2 * m] = cmul(wc, csub(e0, f0));
            dst[p0 + 3 * m] = cmul(wc, csub(e1, f1));
        }
        __syncthreads();
        float2* t = src; src = dst; dst = t;
    }
    // final radix-2 stage (s=10, m=1024): twiddle index (u>>10)<<10 = 0 -> w=1
#pragma unroll
    for (int u = tid; u < 1024; u += 256) {
        float2 c0 = src[u];
        float2 c1 = src[u + 1024];
        dst[u]        = cadd(c0, c1);
        dst[u + 1024] = csub(c0, c1);
    }
    __syncthreads();
    return dst;
}

// ---------------------------------------------------------------------------
// Kernel 1: rfft(x, ortho) -> bf16x2 spectrum (channel-major)
// ---------------------------------------------------------------------------
__global__ void __launch_bounds__(256) kfft_fwd(const float* __restrict__ x) {
    __shared__ float2 bufA[NH];
    __shared__ float2 bufB[NH];
    __shared__ float2 wtab[NQ];
    const int tid = threadIdx.x;
    const int row = blockIdx.x;
    const float2* __restrict__ xin =
        reinterpret_cast<const float2*>(x) + (size_t)row * NH;

#pragma unroll
    for (int i = tid; i < NH; i += 256) bufA[i] = xin[i];
#pragma unroll
    for (int t = tid; t < NQ; t += 256) {
        float s, c;
        sincospif(-(float)t * (2.0f / NH), &s, &c);
        wtab[t] = make_float2(c, s);
    }
    __syncthreads();

    float2* Z = stockham2048_r4<false>(bufA, bufB, wtab, tid);

    __nv_bfloat162* __restrict__ out = g_specA + (size_t)row * MODES;
    for (int k = tid; k < MODES; k += 256) {
        int k2 = k & (NH - 1);
        int kr = (NH - k2) & (NH - 1);
        float2 zk = Z[k2];
        float2 zr = Z[kr];
        float2 xe = make_float2(0.5f * (zk.x + zr.x), 0.5f * (zk.y - zr.y));
        float2 xo = make_float2(0.5f * (zk.y + zr.y), -0.5f * (zk.x - zr.x));
        float s, c;
        sincospif(-(float)k * (1.0f / NH), &s, &c);
        float2 t = make_float2(fmaf(c, xo.x, -s * xo.y),
                               fmaf(c, xo.y,  s * xo.x));
        out[k] = __floats2bfloat162_rn((xe.x + t.x) * ORTHO_INV,
                                       (xe.y + t.y) * ORTHO_INV);
    }
}

// ---------------------------------------------------------------------------
// Kernel 2: blockwise complex 2-layer MLP via mma.sync (bf16 HMMA).
// (unchanged from round 6 — measured win, do not perturb)
// ---------------------------------------------------------------------------
__device__ __forceinline__ float softshrink(float v) {
    return v > LAM ? v - LAM : (v < -LAM ? v + LAM : 0.0f);
}

#define SMEM_MLP_WORDS 51584
#define SMEM_MLP_BYTES (SMEM_MLP_WORDS * 4)
#define W2_BASE 19200
#define A_BASE  38400

#define MMA16816(C, A, B0, B1)                                              \
    asm volatile("mma.sync.aligned.m16n8k16.row.col.f32.bf16.bf16.f32 "     \
        "{%0,%1,%2,%3}, {%4,%5,%6,%7}, {%8,%9}, {%0,%1,%2,%3};"             \
        : "+f"((C)[0]), "+f"((C)[1]), "+f"((C)[2]), "+f"((C)[3])            \
        : "r"((A)[0]), "r"((A)[1]), "r"((A)[2]), "r"((A)[3]),               \
          "r"(B0), "r"(B1))

__global__ void __launch_bounds__(256, 1) kmlp_mma(
    const float* __restrict__ w1_re, const float* __restrict__ w1_im,
    const float* __restrict__ w2_re, const float* __restrict__ w2_im,
    const float* __restrict__ b1_re, const float* __restrict__ b1_im,
    const float* __restrict__ b2_re, const float* __restrict__ b2_im)
{
    extern __shared__ uint32_t smw[];
    __nv_bfloat16* w16 = reinterpret_cast<__nv_bfloat16*>(smw);
    float* sB1 = reinterpret_cast<float*>(smw + 51200);
    float* sB2 = reinterpret_cast<float*>(smw + 51392);

    const int tid  = threadIdx.x;
    const int warp = tid >> 5;
    const int lane = tid & 31;
    const int qr   = lane >> 2;   // 0..7
    const int qc   = lane & 3;    // 0..3
    const int nb   = blockIdx.x & 7;
    const int b    = blockIdx.x >> 3;

    // Build both interleaved weight matrices (B operand, [o][k], stride 200)
    const int wb = nb * 9216;
    for (int idx = tid; idx < 192 * 192; idx += 256) {
        int o = idx / 192, k = idx - o * 192;
        int i = k >> 1, j = o >> 1;
        float re1 = w1_re[wb + i * 96 + j], im1 = w1_im[wb + i * 96 + j];
        float re2 = w2_re[wb + i * 96 + j], im2 = w2_im[wb + i * 96 + j];
        float v1 = (k & 1) ? ((o & 1) ? re1 : -im1) : ((o & 1) ? im1 : re1);
        float v2 = (k & 1) ? ((o & 1) ? re2 : -im2) : ((o & 1) ? im2 : re2);
        w16[o * 200 + k]               = __float2bfloat16(v1);
        w16[W2_BASE * 2 + o * 200 + k] = __float2bfloat16(v2);
    }
    if (tid < 96) {
        sB1[2 * tid] = b1_re[nb * 96 + tid]; sB1[2 * tid + 1] = b1_im[nb * 96 + tid];
        sB2[2 * tid] = b2_re[nb * 96 + tid]; sB2[2 * tid + 1] = b2_im[nb * 96 + tid];
    }

    const size_t chbase = (size_t)b * 768 + (size_t)nb * 96;
    const uint32_t* __restrict__ specA = reinterpret_cast<const uint32_t*>(g_specA);

    for (int tile = 0; tile < 17; tile++) {
        const int m0 = tile * 128;
        __syncthreads();   // prior-tile readers done (and weight build on iter 0)
        // ---- stage A tile: 128 modes x 96 channels (bf16x2 per channel)
        for (int idx = tid; idx < 96 * 128; idx += 256) {
            int ch = idx >> 7, r = idx & 127;
            int m = m0 + r;
            uint32_t v = (m < MODES) ? specA[(chbase + ch) * MODES + m] : 0u;
            smw[A_BASE + r * 100 + ch] = v;
        }
        __syncthreads();

        const int rw = warp * 16 + qr;   // A row for a0 within tile
        float acc[24][4];
#pragma unroll
        for (int nt = 0; nt < 24; nt++)
#pragma unroll
            for (int j = 0; j < 4; j++) acc[nt][j] = 0.0f;

        // ---- layer 1: acc = A x W1
        for (int kk = 0; kk < 12; kk++) {
            const int aw = A_BASE + rw * 100 + kk * 8 + qc;
            uint32_t a[4];
            a[0] = smw[aw];       a[1] = smw[aw + 800];
            a[2] = smw[aw + 4];   a[3] = smw[aw + 804];
            const int bw = qr * 100 + kk * 8 + qc;
#pragma unroll
            for (int nt = 0; nt < 24; nt++) {
                uint32_t b0 = smw[bw + nt * 800];
                uint32_t b1 = smw[bw + nt * 800 + 4];
                MMA16816(acc[nt], a, b0, b1);
            }
        }

        // ---- interlayer: bias + CReLU, pack accs into layer-2 A fragments
        uint32_t af[12][4];
#pragma unroll
        for (int nt = 0; nt < 24; nt++) {
            int col = nt * 8 + 2 * qc;
            float2 bv = *reinterpret_cast<float2*>(&sB1[col]);
            float f0 = fmaxf(acc[nt][0] + bv.x, 0.0f);
            float f1 = fmaxf(acc[nt][1] + bv.y, 0.0f);
            float f2 = fmaxf(acc[nt][2] + bv.x, 0.0f);
            float f3 = fmaxf(acc[nt][3] + bv.y, 0.0f);
            __nv_bfloat162 p01 = __floats2bfloat162_rn(f0, f1);
            __nv_bfloat162 p23 = __floats2bfloat162_rn(f2, f3);
            af[nt >> 1][(nt & 1) ? 2 : 0] = *reinterpret_cast<uint32_t*>(&p01);
            af[nt >> 1][(nt & 1) ? 3 : 1] = *reinterpret_cast<uint32_t*>(&p23);
        }

        // ---- layer 2: acc = CReLU(h) x W2
#pragma unroll
        for (int nt = 0; nt < 24; nt++)
#pragma unroll
            for (int j = 0; j < 4; j++) acc[nt][j] = 0.0f;
#pragma unroll
        for (int kk = 0; kk < 12; kk++) {
            const int bw = W2_BASE + qr * 100 + kk * 8 + qc;
#pragma unroll
            for (int nt = 0; nt < 24; nt++) {
                uint32_t b0 = smw[bw + nt * 800];
                uint32_t b1 = smw[bw + nt * 800 + 4];
                MMA16816(acc[nt], af[kk], b0, b1);
            }
        }

        // ---- epilogue: bias + softshrink, scatter float2 to g_specO
        const int mlo = m0 + warp * 16 + qr;
        const int mhi = mlo + 8;
        const bool vlo = mlo < MODES, vhi = mhi < MODES;
#pragma unroll
        for (int nt = 0; nt < 24; nt++) {
            int col = nt * 8 + 2 * qc;
            int ch  = col >> 1;
            float2 bv = *reinterpret_cast<float2*>(&sB2[col]);
            size_t base = (chbase + ch) * MODES;
            if (vlo)
                g_specO[base + mlo] = make_float2(softshrink(acc[nt][0] + bv.x),
                                                  softshrink(acc[nt][1] + bv.y));
            if (vhi)
                g_specO[base + mhi] = make_float2(softshrink(acc[nt][2] + bv.x),
                                                  softshrink(acc[nt][3] + bv.y));
        }
    }
}

// ---------------------------------------------------------------------------
// Kernel 3: irfft(ortho) per row + residual add, reads g_specO.
// ---------------------------------------------------------------------------
__global__ void __launch_bounds__(256) kfft_inv(const float* __restrict__ x,
                                                float* __restrict__ y) {
    __shared__ float2 bufA[NH];
    __shared__ float2 bufB[NH];
    __shared__ float2 wtab[NQ];
    const int tid = threadIdx.x;
    const int row = blockIdx.x;
    const float2* __restrict__ spec = g_specO + (size_t)row * MODES;

#pragma unroll
    for (int t = tid; t < NQ; t += 256) {
        float s, c;
        sincospif((float)t * (2.0f / NH), &s, &c);
        wtab[t] = make_float2(c, s);
    }
    for (int j = tid; j < NH; j += 256) {
        float2 xj = spec[j];
        float2 xr = spec[NH - j];
        if (j == 0) { xj.y = 0.0f; xr.y = 0.0f; }
        float2 A = make_float2(xj.x + xr.x, xj.y - xr.y);
        float2 D = make_float2(xj.x - xr.x, xj.y + xr.y);
        float s, c;
        sincospif((float)j * (1.0f / NH), &s, &c);
        float2 Bv = make_float2(fmaf(c, D.x, -s * D.y),
                                fmaf(c, D.y,  s * D.x));
        bufA[j] = make_float2(A.x - Bv.y, A.y + Bv.x);
    }
    __syncthreads();

    float2* Zr = stockham2048_r4<true>(bufA, bufB, wtab, tid);

    const float2* __restrict__ xin =
        reinterpret_cast<const float2*>(x) + (size_t)row * NH;
    float2* __restrict__ yout =
        reinterpret_cast<float2*>(y) + (size_t)row * NH;
    for (int n = tid; n < NH; n += 256) {
        float2 z  = Zr[n];
        float2 bv = xin[n];
        yout[n] = make_float2(fmaf(z.x, ORTHO_INV, bv.x),
                              fmaf(z.y, ORTHO_INV, bv.y));
    }
}

// ---------------------------------------------------------------------------
extern "C" void kernel_launch(void* const* d_in, const int* in_sizes, int n_in,
                              void* d_out, int out_size) {
    (void)in_sizes; (void)n_in; (void)out_size;
    const float* x     = (const float*)d_in[0];
    const float* w1_re = (const float*)d_in[1];
    const float* w1_im = (const float*)d_in[2];
    const float* w2_re = (const float*)d_in[3];
    const float* w2_im = (const float*)d_in[4];
    const float* b1_re = (const float*)d_in[5];
    const float* b1_im = (const float*)d_in[6];
    const float* b2_re = (const float*)d_in[7];
    const float* b2_im = (const float*)d_in[8];
    float* y = (float*)d_out;

    kfft_fwd<<<NUM_ROWS, 256>>>(x);

    cudaFuncSetAttribute(kmlp_mma, cudaFuncAttributeMaxDynamicSharedMemorySize,
                         SMEM_MLP_BYTES);
    kmlp_mma<<<128, 256, SMEM_MLP_BYTES>>>(w1_re, w1_im, w2_re, w2_im,
                                           b1_re, b1_im, b2_re, b2_im);

    kfft_inv<<<NUM_ROWS, 256>>>(x, y);
}

// round 15
// speedup vs baseline: 3.0018x; 1.0599x over previous
#include <cuda_runtime.h>
#include <cuda_bf16.h>
#include <math.h>
#include <stdint.h>

#define NUM_ROWS 12288      // 16 * 768
#define NPT 4096
#define NH  2048
#define NQ  1024
#define MODES 2049
#define LAM 0.01f
#define ORTHO_INV 0.015625f // 1/sqrt(4096)

// bf16x2 spectrum (MLP input), channel-major [row_ch][mode]
static __device__ __nv_bfloat162 g_specA[(size_t)NUM_ROWS * MODES];
// fp32 MLP output spectrum, channel-major [row_ch][mode]
static __device__ float2 g_specO[(size_t)NUM_ROWS * MODES];

__device__ __forceinline__ float2 cmul(float2 a, float2 b) {
    return make_float2(fmaf(a.x, b.x, -a.y * b.y), fmaf(a.x, b.y, a.y * b.x));
}
__device__ __forceinline__ float2 cadd(float2 a, float2 b) {
    return make_float2(a.x + b.x, a.y + b.y);
}
__device__ __forceinline__ float2 csub(float2 a, float2 b) {
    return make_float2(a.x - b.x, a.y - b.y);
}

// ===========================================================================
// Shared-memory Stockham FFT, 2048 points, 256 threads.
// 5 fused double-stages + 1 final radix-2 stage. (R10 measured win — frozen.)
// ===========================================================================
template <bool INV>
__device__ __forceinline__ float2* stockham2048_r4(float2* src, float2* dst,
                                                   const float2* __restrict__ wtab,
                                                   int tid) {
#pragma unroll
    for (int s = 0; s < 10; s += 2) {
        const int m = 1 << s;
#pragma unroll
        for (int u = tid; u < 512; u += 256) {
            float2 z0 = src[u];
            float2 z1 = src[u + 512];
            float2 z2 = src[u + 1024];
            float2 z3 = src[u + 1536];
            float2 w  = wtab[(u >> s) << s];

            float2 e0 = cadd(z0, z2);
            float2 e1 = cmul(w, csub(z0, z2));
            float2 f0 = cadd(z1, z3);
            float2 t1 = cmul(w, csub(z1, z3));
            float2 f1 = INV ? make_float2(-t1.y, t1.x)
                            : make_float2( t1.y, -t1.x);

            float2 wc = make_float2(fmaf(w.x, w.x, -w.y * w.y), 2.0f * w.x * w.y);

            int p0 = ((u >> s) << (s + 2)) | (u & (m - 1));
            dst[p0]         = cadd(e0, f0);
            dst[p0 + m]     = cadd(e1, f1);
            dst[p0 + 2 * m] = cmul(wc, csub(e0, f0));
            dst[p0 + 3 * m] = cmul(wc, csub(e1, f1));
        }
        __syncthreads();
        float2* t = src; src = dst; dst = t;
    }
#pragma unroll
    for (int u = tid; u < 1024; u += 256) {
        float2 c0 = src[u];
        float2 c1 = src[u + 1024];
        dst[u]        = cadd(c0, c1);
        dst[u + 1024] = csub(c0, c1);
    }
    __syncthreads();
    return dst;
}

// ---------------------------------------------------------------------------
// Kernel 1: rfft(x, ortho) -> bf16x2 spectrum (channel-major)
// ---------------------------------------------------------------------------
__global__ void __launch_bounds__(256) kfft_fwd(const float* __restrict__ x) {
    __shared__ float2 bufA[NH];
    __shared__ float2 bufB[NH];
    __shared__ float2 wtab[NQ];
    const int tid = threadIdx.x;
    const int row = blockIdx.x;
    const float2* __restrict__ xin =
        reinterpret_cast<const float2*>(x) + (size_t)row * NH;

#pragma unroll
    for (int i = tid; i < NH; i += 256) bufA[i] = xin[i];
#pragma unroll
    for (int t = tid; t < NQ; t += 256) {
        float s, c;
        sincospif(-(float)t * (2.0f / NH), &s, &c);
        wtab[t] = make_float2(c, s);
    }
    __syncthreads();

    float2* Z = stockham2048_r4<false>(bufA, bufB, wtab, tid);

    __nv_bfloat162* __restrict__ out = g_specA + (size_t)row * MODES;
    for (int k = tid; k < MODES; k += 256) {
        int k2 = k & (NH - 1);
        int kr = (NH - k2) & (NH - 1);
        float2 zk = Z[k2];
        float2 zr = Z[kr];
        float2 xe = make_float2(0.5f * (zk.x + zr.x), 0.5f * (zk.y - zr.y));
        float2 xo = make_float2(0.5f * (zk.y + zr.y), -0.5f * (zk.x - zr.x));
        float s, c;
        sincospif(-(float)k * (1.0f / NH), &s, &c);
        float2 t = make_float2(fmaf(c, xo.x, -s * xo.y),
                               fmaf(c, xo.y,  s * xo.x));
        out[k] = __floats2bfloat162_rn((xe.x + t.x) * ORTHO_INV,
                                       (xe.y + t.y) * ORTHO_INV);
    }
}

// ---------------------------------------------------------------------------
// Kernel 2: blockwise complex 2-layer MLP via mma.sync (bf16 HMMA).
// R11 change: 384 threads / 12 warps, 192-mode tiles (3 warps per SMSP for
// latency hiding; 11 tiles instead of 17).
//
// smem word layout (uint32 units):
//   W1:      [0      .. 19200)   192 rows x 100 (conflict-free B loads)
//   W2:      [19200  .. 38400)
//   A tile:  [38400  .. 57216)   192 rows x 98
//   b1:      [57216  .. 57408)   192 floats
//   b2:      [57408  .. 57600)
// ---------------------------------------------------------------------------
__device__ __forceinline__ float softshrink(float v) {
    return v > LAM ? v - LAM : (v < -LAM ? v + LAM : 0.0f);
}

#define MLP_THREADS 384
#define MLP_TILE 192
#define MLP_NTILES 11           // ceil(2049 / 192)
#define A_STRIDE 98
#define SMEM_MLP_WORDS 57600
#define SMEM_MLP_BYTES (SMEM_MLP_WORDS * 4)
#define W2_BASE 19200
#define A_BASE  38400
#define B1_BASE 57216
#define B2_BASE 57408

#define MMA16816(C, A, B0, B1)                                              \
    asm volatile("mma.sync.aligned.m16n8k16.row.col.f32.bf16.bf16.f32 "     \
        "{%0,%1,%2,%3}, {%4,%5,%6,%7}, {%8,%9}, {%0,%1,%2,%3};"             \
        : "+f"((C)[0]), "+f"((C)[1]), "+f"((C)[2]), "+f"((C)[3])            \
        : "r"((A)[0]), "r"((A)[1]), "r"((A)[2]), "r"((A)[3]),               \
          "r"(B0), "r"(B1))

__global__ void __launch_bounds__(MLP_THREADS, 1) kmlp_mma(
    const float* __restrict__ w1_re, const float* __restrict__ w1_im,
    const float* __restrict__ w2_re, const float* __restrict__ w2_im,
    const float* __restrict__ b1_re, const float* __restrict__ b1_im,
    const float* __restrict__ b2_re, const float* __restrict__ b2_im)
{
    extern __shared__ uint32_t smw[];
    __nv_bfloat16* w16 = reinterpret_cast<__nv_bfloat16*>(smw);
    float* sB1 = reinterpret_cast<float*>(smw + B1_BASE);
    float* sB2 = reinterpret_cast<float*>(smw + B2_BASE);

    const int tid  = threadIdx.x;
    const int warp = tid >> 5;
    const int lane = tid & 31;
    const int qr   = lane >> 2;   // 0..7
    const int qc   = lane & 3;    // 0..3
    const int nb   = blockIdx.x & 7;
    const int b    = blockIdx.x >> 3;

    // Build both interleaved weight matrices (B operand, [o][k], stride 200)
    const int wb = nb * 9216;
    for (int idx = tid; idx < 192 * 192; idx += MLP_THREADS) {
        int o = idx / 192, k = idx - o * 192;
        int i = k >> 1, j = o >> 1;
        float re1 = w1_re[wb + i * 96 + j], im1 = w1_im[wb + i * 96 + j];
        float re2 = w2_re[wb + i * 96 + j], im2 = w2_im[wb + i * 96 + j];
        float v1 = (k & 1) ? ((o & 1) ? re1 : -im1) : ((o & 1) ? im1 : re1);
        float v2 = (k & 1) ? ((o & 1) ? re2 : -im2) : ((o & 1) ? im2 : re2);
        w16[o * 200 + k]               = __float2bfloat16(v1);
        w16[W2_BASE * 2 + o * 200 + k] = __float2bfloat16(v2);
    }
    if (tid < 96) {
        sB1[2 * tid] = b1_re[nb * 96 + tid]; sB1[2 * tid + 1] = b1_im[nb * 96 + tid];
        sB2[2 * tid] = b2_re[nb * 96 + tid]; sB2[2 * tid + 1] = b2_im[nb * 96 + tid];
    }

    const size_t chbase = (size_t)b * 768 + (size_t)nb * 96;
    const uint32_t* __restrict__ specA = reinterpret_cast<const uint32_t*>(g_specA);

    for (int tile = 0; tile < MLP_NTILES; tile++) {
        const int m0 = tile * MLP_TILE;
        __syncthreads();   // prior-tile readers done (and weight build on iter 0)
        // ---- stage A tile: 192 modes x 96 channels (bf16x2 per channel)
        for (int idx = tid; idx < 96 * MLP_TILE; idx += MLP_THREADS) {
            int ch = idx / MLP_TILE, r = idx - ch * MLP_TILE;
            int m = m0 + r;
            uint32_t v = (m < MODES) ? specA[(chbase + ch) * MODES + m] : 0u;
            smw[A_BASE + r * A_STRIDE + ch] = v;
        }
        __syncthreads();

        const int rw = warp * 16 + qr;   // A row for a0 within tile
        float acc[24][4];
#pragma unroll
        for (int nt = 0; nt < 24; nt++)
#pragma unroll
            for (int j = 0; j < 4; j++) acc[nt][j] = 0.0f;

        // ---- layer 1: acc = A x W1
        for (int kk = 0; kk < 12; kk++) {
            const int aw = A_BASE + rw * A_STRIDE + kk * 8 + qc;
            uint32_t a[4];
            a[0] = smw[aw];                 a[1] = smw[aw + 8 * A_STRIDE];
            a[2] = smw[aw + 4];             a[3] = smw[aw + 8 * A_STRIDE + 4];
            const int bw = qr * 100 + kk * 8 + qc;
#pragma unroll
            for (int nt = 0; nt < 24; nt++) {
                uint32_t b0 = smw[bw + nt * 800];
                uint32_t b1 = smw[bw + nt * 800 + 4];
                MMA16816(acc[nt], a, b0, b1);
            }
        }

        // ---- interlayer: bias + CReLU, pack accs into layer-2 A fragments
        uint32_t af[12][4];
#pragma unroll
        for (int nt = 0; nt < 24; nt++) {
            int col = nt * 8 + 2 * qc;
            float2 bv = *reinterpret_cast<float2*>(&sB1[col]);
            float f0 = fmaxf(acc[nt][0] + bv.x, 0.0f);
            float f1 = fmaxf(acc[nt][1] + bv.y, 0.0f);
            float f2 = fmaxf(acc[nt][2] + bv.x, 0.0f);
            float f3 = fmaxf(acc[nt][3] + bv.y, 0.0f);
            __nv_bfloat162 p01 = __floats2bfloat162_rn(f0, f1);
            __nv_bfloat162 p23 = __floats2bfloat162_rn(f2, f3);
            af[nt >> 1][(nt & 1) ? 2 : 0] = *reinterpret_cast<uint32_t*>(&p01);
            af[nt >> 1][(nt & 1) ? 3 : 1] = *reinterpret_cast<uint32_t*>(&p23);
        }

        // ---- layer 2: acc = CReLU(h) x W2
#pragma unroll
        for (int nt = 0; nt < 24; nt++)
#pragma unroll
            for (int j = 0; j < 4; j++) acc[nt][j] = 0.0f;
#pragma unroll
        for (int kk = 0; kk < 12; kk++) {
            const int bw = W2_BASE + qr * 100 + kk * 8 + qc;
#pragma unroll
            for (int nt = 0; nt < 24; nt++) {
                uint32_t b0 = smw[bw + nt * 800];
                uint32_t b1 = smw[bw + nt * 800 + 4];
                MMA16816(acc[nt], af[kk], b0, b1);
            }
        }

        // ---- epilogue: bias + softshrink, scatter float2 to g_specO
        const int mlo = m0 + warp * 16 + qr;
        const int mhi = mlo + 8;
        const bool vlo = mlo < MODES, vhi = mhi < MODES;
#pragma unroll
        for (int nt = 0; nt < 24; nt++) {
            int col = nt * 8 + 2 * qc;
            int ch  = col >> 1;
            float2 bv = *reinterpret_cast<float2*>(&sB2[col]);
            size_t base = (chbase + ch) * MODES;
            if (vlo)
                g_specO[base + mlo] = make_float2(softshrink(acc[nt][0] + bv.x),
                                                  softshrink(acc[nt][1] + bv.y));
            if (vhi)
                g_specO[base + mhi] = make_float2(softshrink(acc[nt][2] + bv.x),
                                                  softshrink(acc[nt][3] + bv.y));
        }
    }
}

// ---------------------------------------------------------------------------
// Kernel 3: irfft(ortho) per row + residual add, reads g_specO.
// ---------------------------------------------------------------------------
__global__ void __launch_bounds__(256) kfft_inv(const float* __restrict__ x,
                                                float* __restrict__ y) {
    __shared__ float2 bufA[NH];
    __shared__ float2 bufB[NH];
    __shared__ float2 wtab[NQ];
    const int tid = threadIdx.x;
    const int row = blockIdx.x;
    const float2* __restrict__ spec = g_specO + (size_t)row * MODES;

#pragma unroll
    for (int t = tid; t < NQ; t += 256) {
        float s, c;
        sincospif((float)t * (2.0f / NH), &s, &c);
        wtab[t] = make_float2(c, s);
    }
    for (int j = tid; j < NH; j += 256) {
        float2 xj = spec[j];
        float2 xr = spec[NH - j];
        if (j == 0) { xj.y = 0.0f; xr.y = 0.0f; }
        float2 A = make_float2(xj.x + xr.x, xj.y - xr.y);
        float2 D = make_float2(xj.x - xr.x, xj.y + xr.y);
        float s, c;
        sincospif((float)j * (1.0f / NH), &s, &c);
        float2 Bv = make_float2(fmaf(c, D.x, -s * D.y),
                                fmaf(c, D.y,  s * D.x));
        bufA[j] = make_float2(A.x - Bv.y, A.y + Bv.x);
    }
    __syncthreads();

    float2* Zr = stockham2048_r4<true>(bufA, bufB, wtab, tid);

    const float2* __restrict__ xin =
        reinterpret_cast<const float2*>(x) + (size_t)row * NH;
    float2* __restrict__ yout =
        reinterpret_cast<float2*>(y) + (size_t)row * NH;
    for (int n = tid; n < NH; n += 256) {
        float2 z  = Zr[n];
        float2 bv = xin[n];
        yout[n] = make_float2(fmaf(z.x, ORTHO_INV, bv.x),
                              fmaf(z.y, ORTHO_INV, bv.y));
    }
}

// ---------------------------------------------------------------------------
extern "C" void kernel_launch(void* const* d_in, const int* in_sizes, int n_in,
                              void* d_out, int out_size) {
    (void)in_sizes; (void)n_in; (void)out_size;
    const float* x     = (const float*)d_in[0];
    const float* w1_re = (const float*)d_in[1];
    const float* w1_im = (const float*)d_in[2];
    const float* w2_re = (const float*)d_in[3];
    const float* w2_im = (const float*)d_in[4];
    const float* b1_re = (const float*)d_in[5];
    const float* b1_im = (const float*)d_in[6];
    const float* b2_re = (const float*)d_in[7];
    const float* b2_im = (const float*)d_in[8];
    float* y = (float*)d_out;

    kfft_fwd<<<NUM_ROWS, 256>>>(x);

    cudaFuncSetAttribute(kmlp_mma, cudaFuncAttributeMaxDynamicSharedMemorySize,
                         SMEM_MLP_BYTES);
    kmlp_mma<<<128, MLP_THREADS, SMEM_MLP_BYTES>>>(w1_re, w1_im, w2_re, w2_im,
                                                   b1_re, b1_im, b2_re, b2_im);

    kfft_inv<<<NUM_ROWS, 256>>>(x, y);
}